// round 11
// baseline (speedup 1.0000x reference)
#include <cuda_runtime.h>
#include <math.h>

#define T_SEQ  1024
#define DMODEL 4096
#define NHEAD  32
#define DNOPE  128
#define DROPE  64
#define DHEAD  192
#define DV     128
#define QRANK  1536
#define KVRANK 512
#define IFF    11008
#define EPSV   1e-6f
#define SCALEV 0.07216878364870323f  // 192^-0.5

// ---------------- scratch ----------------------------------------------------
__device__ float g_x   [T_SEQ * DMODEL];
__device__ float g_qa  [T_SEQ * QRANK];
__device__ float g_qan [T_SEQ * QRANK];
__device__ float g_q   [T_SEQ * NHEAD * DHEAD];
__device__ float g_ckv [T_SEQ * (KVRANK + DROPE)];
__device__ float g_cn  [T_SEQ * KVRANK];
__device__ float g_kv  [T_SEQ * NHEAD * (DNOPE + DV)];
__device__ float g_kf  [T_SEQ * NHEAD * DHEAD];
__device__ float g_vt  [NHEAD * DV * T_SEQ];
__device__ float g_sc  [(long long)NHEAD * T_SEQ * T_SEQ];
__device__ float g_ctx [T_SEQ * NHEAD * DV];
__device__ float g_hres[T_SEQ * DMODEL];
__device__ float g_x2  [T_SEQ * DMODEL];
__device__ float g_gu  [T_SEQ * 2 * IFF];
__device__ float g_y   [T_SEQ * IFF];
// tf32-rounded weight copies
__device__ float g_wqa [QRANK * DMODEL];
__device__ float g_wqb [(NHEAD * DHEAD) * QRANK];
__device__ float g_wkva[(KVRANK + DROPE) * DMODEL];
__device__ float g_wkvb[(NHEAD * (DNOPE + DV)) * KVRANK];
__device__ float g_wo  [DMODEL * DMODEL];
__device__ float g_wgu [(2 * IFF) * DMODEL];
__device__ float g_wdn [DMODEL * IFF];

// ---------------- helpers ----------------------------------------------------
__device__ __forceinline__ unsigned f2tf32(float f) {
    unsigned r;
    asm("cvt.rna.tf32.f32 %0, %1;" : "=r"(r) : "f"(f));
    return r;
}
__device__ __forceinline__ float rnd(float f) { return __uint_as_float(f2tf32(f)); }

__device__ __forceinline__ void mma8(float c[4], const unsigned a[4], const unsigned b[2]) {
    asm volatile(
        "mma.sync.aligned.m16n8k8.row.col.f32.tf32.tf32.f32 "
        "{%0,%1,%2,%3},{%4,%5,%6,%7},{%8,%9},{%0,%1,%2,%3};\n"
        : "+f"(c[0]), "+f"(c[1]), "+f"(c[2]), "+f"(c[3])
        : "r"(a[0]), "r"(a[1]), "r"(a[2]), "r"(a[3]),
          "r"(b[0]), "r"(b[1]));
}

__device__ __forceinline__ void cp16(unsigned dst, const void* src, bool pred) {
    asm volatile("cp.async.cg.shared.global [%0], [%1], 16, %2;\n"
                 :: "r"(dst), "l"(src), "r"(pred ? 16 : 0));
}
#define CP_COMMIT() asm volatile("cp.async.commit_group;\n" ::: "memory")
#define CP_WAIT1()  asm volatile("cp.async.wait_group 1;\n" ::: "memory")

// ---------------- tf32 tensor-core GEMM (TN): C[m,n] = sum_k A[m,k]*B[n,k] --
// CTA tile 128(M)x256(N), BK=32, 8 warps (2x4), warp tile 64x64 (4x8 m16n8k8).
// Inputs must be tf32-pre-rounded (bits used directly; no in-loop cvt).
// grid = (M/128, ceil(N/256), batch). R: optional residual. roundC: rna-round C.
// causal: skip blocks fully above diagonal. kcap: clamp K to m0+128.
#define SST  36                       // padded row stride (floats)
#define SSTG ((128 + 256) * SST)      // stage stride (floats)
#define GSMEM_SZ (3 * SSTG * 4)

__global__ void __launch_bounds__(256, 1) gemm_tc(
    const float* __restrict__ A, int lda, long long sA,
    const float* __restrict__ B, int ldb, long long sB,
    float*       __restrict__ C, int ldc, long long sC,
    const float* __restrict__ R,
    int N, int K, int causal, int kcap, int roundC)
{
    extern __shared__ float sh[];
    long long z = blockIdx.z;
    A += z * sA; B += z * sB; C += z * sC;
    int m0 = blockIdx.x * 128, n0 = blockIdx.y * 256;
    if (causal && n0 > m0 + 127) return;
    if (kcap) { int kl = m0 + 128; if (kl < K) K = kl; }

    int tid = threadIdx.x;
    int lr = tid >> 1, lcb = (tid & 1) << 4;          // A loader: 2 thr/row
    int wid = tid >> 5, wm = wid & 1, wn = wid >> 1;  // warps 2(M) x 4(N)
    int lane = tid & 31, g = lane >> 2, t = lane & 3;

    unsigned sh_u = (unsigned)__cvta_generic_to_shared(sh);
    const float* Ap = A + (long long)(m0 + lr) * lda + lcb;
    bool bok = (n0 + tid) < N;
    const float* Bp = B + (long long)(n0 + tid) * ldb;

    float acc[4][8][4];
#pragma unroll
    for (int i = 0; i < 4; i++)
#pragma unroll
        for (int j = 0; j < 8; j++)
#pragma unroll
            for (int e = 0; e < 4; e++) acc[i][j][e] = 0.f;

    int nk = K >> 5;

#define PREFETCH(K0, S) do {                                                   \
        unsigned ab = sh_u + ((S) * SSTG + lr * SST + lcb) * 4;                \
        unsigned bb = sh_u + ((S) * SSTG + 128 * SST + tid * SST) * 4;         \
        const float* ap_ = Ap + (K0);                                          \
        const float* bp_ = Bp + (K0);                                          \
        _Pragma("unroll")                                                      \
        for (int j = 0; j < 4; j++) cp16(ab + j * 16, ap_ + j * 4, true);      \
        _Pragma("unroll")                                                      \
        for (int j = 0; j < 8; j++) cp16(bb + j * 16, bp_ + j * 4, bok);       \
    } while (0)

    PREFETCH(0, 0);
    CP_COMMIT();
    if (nk > 1) PREFETCH(32, 1);
    CP_COMMIT();

    for (int it = 0; it < nk; it++) {
        CP_WAIT1();
        __syncthreads();
        if (it + 2 < nk) PREFETCH((it + 2) << 5, (it + 2) % 3);
        CP_COMMIT();

        const unsigned* As = (const unsigned*)(sh + (it % 3) * SSTG);
        const unsigned* Bs = As + 128 * SST;
#pragma unroll
        for (int kk = 0; kk < 4; kk++) {
            unsigned a[4][4], b[8][2];
#pragma unroll
            for (int i = 0; i < 4; i++) {
                const unsigned* p = &As[(wm * 64 + i * 16 + g) * SST + kk * 8 + t];
                a[i][0] = p[0];
                a[i][1] = p[8 * SST];
                a[i][2] = p[4];
                a[i][3] = p[8 * SST + 4];
            }
#pragma unroll
            for (int j = 0; j < 8; j++) {
                const unsigned* p = &Bs[(wn * 64 + j * 8 + g) * SST + kk * 8 + t];
                b[j][0] = p[0];
                b[j][1] = p[4];
            }
#pragma unroll
            for (int i = 0; i < 4; i++)
#pragma unroll
                for (int j = 0; j < 8; j++) mma8(acc[i][j], a[i], b[j]);
        }
        __syncthreads();
    }

#pragma unroll
    for (int i = 0; i < 4; i++) {
        int r0 = m0 + wm * 64 + i * 16 + g;
#pragma unroll
        for (int j = 0; j < 8; j++) {
            int c0 = n0 + wn * 64 + j * 8 + 2 * t;
            if (c0 < N) {
                float v0 = acc[i][j][0], v1 = acc[i][j][1];
                float v2 = acc[i][j][2], v3 = acc[i][j][3];
                if (R) {
                    v0 += R[(long long)r0 * ldc + c0];
                    v1 += R[(long long)r0 * ldc + c0 + 1];
                    v2 += R[(long long)(r0 + 8) * ldc + c0];
                    v3 += R[(long long)(r0 + 8) * ldc + c0 + 1];
                }
                if (roundC) { v0 = rnd(v0); v1 = rnd(v1); v2 = rnd(v2); v3 = rnd(v3); }
                *(float2*)&C[(long long)r0 * ldc + c0]       = make_float2(v0, v1);
                *(float2*)&C[(long long)(r0 + 8) * ldc + c0] = make_float2(v2, v3);
            }
        }
    }
}

// ---------------- weight rounding: out = tf32_rna(in), float4 grid-stride ---
__global__ void __launch_bounds__(256) round_w(
    const float4* __restrict__ in, float4* __restrict__ out, int n4)
{
    for (int i = blockIdx.x * 256 + threadIdx.x; i < n4; i += gridDim.x * 256) {
        float4 v = in[i];
        v.x = rnd(v.x); v.y = rnd(v.y); v.z = rnd(v.z); v.w = rnd(v.w);
        out[i] = v;
    }
}

// ---------------- V transpose (kv already tf32-rounded) ----------------------
__global__ void __launch_bounds__(256) transpose_v(
    const float* __restrict__ kv, float* __restrict__ vt)
{
    __shared__ float tile[32][33];
    int hd0 = blockIdx.x * 32, t0 = blockIdx.y * 32;
    int x = threadIdx.x & 31, ybase = threadIdx.x >> 5;
    for (int y = ybase; y < 32; y += 8) {
        int hd = hd0 + x, tt = t0 + y;
        tile[y][x] = kv[(long long)tt * (NHEAD * 256) + (hd >> 7) * 256 + DNOPE + (hd & 127)];
    }
    __syncthreads();
    for (int y = ybase; y < 32; y += 8) {
        int hd = hd0 + y, tt = t0 + x;
        vt[(long long)hd * T_SEQ + tt] = tile[x][y];
    }
}

// ---------------- RMSNorm (tf32-rounded output) -------------------------------
__global__ void __launch_bounds__(256) rmsnorm_k(
    const float* __restrict__ in, int ldin,
    const float* __restrict__ w,
    float* __restrict__ out, int ldout, int cols)
{
    int r = blockIdx.x;
    const float* xr = in + (long long)r * ldin;
    float* orow = out + (long long)r * ldout;
    float s = 0.f;
    for (int i = threadIdx.x; i < cols; i += 256) { float a = xr[i]; s += a * a; }
#pragma unroll
    for (int o = 16; o; o >>= 1) s += __shfl_xor_sync(0xffffffffu, s, o);
    __shared__ float sred[8];
    __shared__ float srs;
    if ((threadIdx.x & 31) == 0) sred[threadIdx.x >> 5] = s;
    __syncthreads();
    if (threadIdx.x == 0) {
        float tot = 0.f;
#pragma unroll
        for (int i = 0; i < 8; i++) tot += sred[i];
        srs = rsqrtf(tot / (float)cols + EPSV);
    }
    __syncthreads();
    float rs = srs;
    for (int i = threadIdx.x; i < cols; i += 256)
        orow[i] = rnd(xr[i] * rs * w[i]);
}

// ---------------- RoPE on q_pe, in place (rounded) ----------------------------
__global__ void __launch_bounds__(256) rope_q(
    float* __restrict__ q, const float* __restrict__ cosb, const float* __restrict__ sinb)
{
    int t = blockIdx.x;
    int h = blockIdx.y * 8 + (threadIdx.x >> 5);
    int i = threadIdx.x & 31;
    float* p = q + ((long long)t * NHEAD + h) * DHEAD + DNOPE;
    float a = p[2 * i], b = p[2 * i + 1];
    float c = cosb[t * 32 + i], s = sinb[t * 32 + i];
    __syncwarp();
    p[i]      = rnd(a * c - b * s);
    p[i + 32] = rnd(a * s + b * c);
}

// ---------------- k_full: k_nope | broadcast(roped k_pe) ----------------------
__global__ void __launch_bounds__(256) build_kfull(
    const float* __restrict__ ckv, const float* __restrict__ kv,
    float* __restrict__ kf,
    const float* __restrict__ cosb, const float* __restrict__ sinb)
{
    int t = blockIdx.x;
    __shared__ float kpe[DROPE];
    if (threadIdx.x < 32) {
        int i = threadIdx.x;
        const float* kp = ckv + (long long)t * (KVRANK + DROPE) + KVRANK;
        float a = kp[2 * i], b = kp[2 * i + 1];
        float c = cosb[t * 32 + i], s = sinb[t * 32 + i];
        kpe[i]      = rnd(a * c - b * s);
        kpe[i + 32] = rnd(a * s + b * c);
    }
    __syncthreads();
    for (int idx = threadIdx.x; idx < NHEAD * DNOPE; idx += 256) {
        int h = idx >> 7, d = idx & 127;
        kf[((long long)t * NHEAD + h) * DHEAD + d] =
            kv[((long long)t * NHEAD + h) * (DNOPE + DV) + d];
    }
    for (int idx = threadIdx.x; idx < NHEAD * DROPE; idx += 256) {
        int h = idx >> 6, d = idx & 63;
        kf[((long long)t * NHEAD + h) * DHEAD + DNOPE + d] = kpe[d];
    }
}

// ---------------- causal softmax (scale fused, rounded), in place -------------
__global__ void __launch_bounds__(256) softmax_causal(float* __restrict__ S)
{
    int t = blockIdx.x;
    long long h = blockIdx.y;
    float* row = S + (h * T_SEQ + t) * (long long)T_SEQ;
    int n = t + 1;
    int tid = threadIdx.x;
    float v[4];
#pragma unroll
    for (int j = 0; j < 4; j++) {
        int i = tid + j * 256;
        v[j] = (i < n) ? row[i] * SCALEV : -3.0e38f;
    }
    float m = fmaxf(fmaxf(v[0], v[1]), fmaxf(v[2], v[3]));
#pragma unroll
    for (int o = 16; o; o >>= 1) m = fmaxf(m, __shfl_xor_sync(0xffffffffu, m, o));
    __shared__ float sred[8];
    __shared__ float sres;
    if ((tid & 31) == 0) sred[tid >> 5] = m;
    __syncthreads();
    if (tid == 0) {
        float x = sred[0];
#pragma unroll
        for (int i = 1; i < 8; i++) x = fmaxf(x, sred[i]);
        sres = x;
    }
    __syncthreads();
    m = sres;
    __syncthreads();
    float s = 0.f;
#pragma unroll
    for (int j = 0; j < 4; j++) { v[j] = __expf(v[j] - m); s += v[j]; }
#pragma unroll
    for (int o = 16; o; o >>= 1) s += __shfl_xor_sync(0xffffffffu, s, o);
    if ((tid & 31) == 0) sred[tid >> 5] = s;
    __syncthreads();
    if (tid == 0) {
        float x = 0.f;
#pragma unroll
        for (int i = 0; i < 8; i++) x += sred[i];
        sres = x;
    }
    __syncthreads();
    float inv = 1.f / sres;
#pragma unroll
    for (int j = 0; j < 4; j++) {
        int i = tid + j * 256;
        row[i] = rnd(v[j] * inv);
    }
}

// ---------------- silu(gate) * up (rounded) ----------------------------------
__global__ void __launch_bounds__(256) silu_mul(
    const float* __restrict__ gu, float* __restrict__ y)
{
    long long idx = (long long)blockIdx.x * 256 + threadIdx.x;
    int t = (int)(idx / IFF);
    int i = (int)(idx % IFF);
    float g = gu[(long long)t * (2 * IFF) + i];
    float u = gu[(long long)t * (2 * IFF) + IFF + i];
    y[idx] = rnd(g / (1.f + __expf(-g)) * u);
}

// ---------------- launch ----------------------------------------------------
extern "C" void kernel_launch(void* const* d_in, const int* in_sizes, int n_in,
                              void* d_out, int out_size)
{
    const float* hidden    = (const float*)d_in[0];
    const float* cosb      = (const float*)d_in[1];
    const float* sinb      = (const float*)d_in[2];
    const float* w_ln_in   = (const float*)d_in[3];
    const float* w_q_a     = (const float*)d_in[4];
    const float* w_q_ln    = (const float*)d_in[5];
    const float* w_q_b     = (const float*)d_in[6];
    const float* w_kv_a    = (const float*)d_in[7];
    const float* w_kv_ln   = (const float*)d_in[8];
    const float* w_kv_b    = (const float*)d_in[9];
    const float* w_o       = (const float*)d_in[10];
    const float* w_ln_post = (const float*)d_in[11];
    const float* w_gate_up = (const float*)d_in[12];
    const float* w_down    = (const float*)d_in[13];
    float* out = (float*)d_out;

    static int smem_set = 0;
    if (!smem_set) {
        cudaFuncSetAttribute(gemm_tc,
                             cudaFuncAttributeMaxDynamicSharedMemorySize, GSMEM_SZ);
        smem_set = 1;
    }

    float *x, *qa, *qan, *q, *ckv, *cn, *kv, *kf, *vt, *sc, *ctx, *hres, *x2, *gu, *y;
    float *wqa, *wqb, *wkva, *wkvb, *wo, *wgu, *wdn;
    cudaGetSymbolAddress((void**)&x,    g_x);
    cudaGetSymbolAddress((void**)&qa,   g_qa);
    cudaGetSymbolAddress((void**)&qan,  g_qan);
    cudaGetSymbolAddress((void**)&q,    g_q);
    cudaGetSymbolAddress((void**)&ckv,  g_ckv);
    cudaGetSymbolAddress((void**)&cn,   g_cn);
    cudaGetSymbolAddress((void**)&kv,   g_kv);
    cudaGetSymbolAddress((void**)&kf,   g_kf);
    cudaGetSymbolAddress((void**)&vt,   g_vt);
    cudaGetSymbolAddress((void**)&sc,   g_sc);
    cudaGetSymbolAddress((void**)&ctx,  g_ctx);
    cudaGetSymbolAddress((void**)&hres, g_hres);
    cudaGetSymbolAddress((void**)&x2,   g_x2);
    cudaGetSymbolAddress((void**)&gu,   g_gu);
    cudaGetSymbolAddress((void**)&y,    g_y);
    cudaGetSymbolAddress((void**)&wqa,  g_wqa);
    cudaGetSymbolAddress((void**)&wqb,  g_wqb);
    cudaGetSymbolAddress((void**)&wkva, g_wkva);
    cudaGetSymbolAddress((void**)&wkvb, g_wkvb);
    cudaGetSymbolAddress((void**)&wo,   g_wo);
    cudaGetSymbolAddress((void**)&wgu,  g_wgu);
    cudaGetSymbolAddress((void**)&wdn,  g_wdn);

    // 0. round all weights to tf32 (rna) once per call
    round_w<<<1184, 256>>>((const float4*)w_q_a,     (float4*)wqa,  QRANK * DMODEL / 4);
    round_w<<<1184, 256>>>((const float4*)w_q_b,     (float4*)wqb,  NHEAD * DHEAD * QRANK / 4);
    round_w<<<1184, 256>>>((const float4*)w_kv_a,    (float4*)wkva, (KVRANK + DROPE) * DMODEL / 4);
    round_w<<<1184, 256>>>((const float4*)w_kv_b,    (float4*)wkvb, NHEAD * 256 * KVRANK / 4);
    round_w<<<1184, 256>>>((const float4*)w_o,       (float4*)wo,   DMODEL * DMODEL / 4);
    round_w<<<1184, 256>>>((const float4*)w_gate_up, (float4*)wgu,  2 * IFF * DMODEL / 4);
    round_w<<<1184, 256>>>((const float4*)w_down,    (float4*)wdn,  DMODEL * IFF / 4);

    // 1. x = rmsnorm(hidden)           (tf32-rounded)
    rmsnorm_k<<<T_SEQ, 256>>>(hidden, DMODEL, w_ln_in, x, DMODEL, DMODEL);
    // 2. q_a = x @ w_q_a^T
    gemm_tc<<<dim3(8, 6, 1), 256, GSMEM_SZ>>>(
        x, DMODEL, 0, wqa, DMODEL, 0, qa, QRANK, 0, nullptr, QRANK, DMODEL, 0, 0, 0);
    // 3. q_a = rmsnorm(q_a)
    rmsnorm_k<<<T_SEQ, 256>>>(qa, QRANK, w_q_ln, qan, QRANK, QRANK);
    // 4. q = q_a @ w_q_b^T  (rounded: feeds QK as A)
    gemm_tc<<<dim3(8, 24, 1), 256, GSMEM_SZ>>>(
        qan, QRANK, 0, wqb, QRANK, 0, q, NHEAD * DHEAD, 0, nullptr, NHEAD * DHEAD, QRANK, 0, 0, 1);
    // 5. ckv = x @ w_kv_a^T
    gemm_tc<<<dim3(8, 3, 1), 256, GSMEM_SZ>>>(
        x, DMODEL, 0, wkva, DMODEL, 0, ckv, KVRANK + DROPE, 0, nullptr, KVRANK + DROPE, DMODEL, 0, 0, 0);
    // 6. c_n = rmsnorm(ckv[:, :512])
    rmsnorm_k<<<T_SEQ, 256>>>(ckv, KVRANK + DROPE, w_kv_ln, cn, KVRANK, KVRANK);
    // 7. kv = c_n @ w_kv_b^T  (rounded: feeds kf / vt)
    gemm_tc<<<dim3(8, 32, 1), 256, GSMEM_SZ>>>(
        cn, KVRANK, 0, wkvb, KVRANK, 0, kv, NHEAD * 256, 0, nullptr, NHEAD * 256, KVRANK, 0, 0, 1);
    // 8. rope q_pe in place (rounded)
    rope_q<<<dim3(T_SEQ, NHEAD / 8), 256>>>(q, cosb, sinb);
    // 9. k_full
    build_kfull<<<T_SEQ, 256>>>(ckv, kv, kf, cosb, sinb);
    // 9b. vt = V^T per head
    transpose_v<<<dim3((NHEAD * DV) / 32, T_SEQ / 32), 256>>>(kv, vt);
    // 10. scores = q @ kf^T  (batched over heads; causal-skip)
    gemm_tc<<<dim3(8, 4, NHEAD), 256, GSMEM_SZ>>>(
        q, NHEAD * DHEAD, (long long)DHEAD,
        kf, NHEAD * DHEAD, (long long)DHEAD,
        sc, T_SEQ, (long long)T_SEQ * T_SEQ,
        nullptr, T_SEQ, DHEAD, 1, 0, 0);
    // 11. causal softmax (rounded output)
    softmax_causal<<<dim3(T_SEQ, NHEAD), 256>>>(sc);
    // 12. ctx = probs @ vt^T  (K capped; rounded: feeds w_o as A)
    gemm_tc<<<dim3(8, 1, NHEAD), 256, GSMEM_SZ>>>(
        sc, T_SEQ, (long long)T_SEQ * T_SEQ,
        vt, T_SEQ, (long long)DV * T_SEQ,
        ctx, NHEAD * DV, (long long)DV,
        nullptr, DV, T_SEQ, 0, 1, 1);
    // 13. h_res = ctx @ w_o^T + hidden  (NOT rounded: residual path)
    gemm_tc<<<dim3(8, 16, 1), 256, GSMEM_SZ>>>(
        ctx, DMODEL, 0, wo, DMODEL, 0, hres, DMODEL, 0, hidden, DMODEL, DMODEL, 0, 0, 0);
    // 14. x2 = rmsnorm(h_res)
    rmsnorm_k<<<T_SEQ, 256>>>(hres, DMODEL, w_ln_post, x2, DMODEL, DMODEL);
    // 15. gu = x2 @ w_gate_up^T
    gemm_tc<<<dim3(8, 86, 1), 256, GSMEM_SZ>>>(
        x2, DMODEL, 0, wgu, DMODEL, 0, gu, 2 * IFF, 0, nullptr, 2 * IFF, DMODEL, 0, 0, 0);
    // 16. y = silu(gate) * up (rounded)
    silu_mul<<<(T_SEQ * IFF) / 256, 256>>>(gu, y);
    // 17. out = y @ w_down^T + h_res  (NOT rounded)
    gemm_tc<<<dim3(8, 16, 1), 256, GSMEM_SZ>>>(
        y, IFF, 0, wdn, IFF, 0, out, DMODEL, 0, hres, DMODEL, IFF, 0, 0, 0);
}

// round 12
// speedup vs baseline: 1.6473x; 1.6473x over previous
#include <cuda_runtime.h>
#include <math.h>

#define T_SEQ  1024
#define DMODEL 4096
#define NHEAD  32
#define DNOPE  128
#define DROPE  64
#define DHEAD  192
#define DV     128
#define QRANK  1536
#define KVRANK 512
#define IFF    11008
#define EPSV   1e-6f
#define SCALEV 0.07216878364870323f  // 192^-0.5

// ---------------- scratch ----------------------------------------------------
__device__ float g_x   [T_SEQ * DMODEL];
__device__ float g_qa  [T_SEQ * QRANK];
__device__ float g_qan [T_SEQ * QRANK];
__device__ float g_q   [T_SEQ * NHEAD * DHEAD];
__device__ float g_ckv [T_SEQ * (KVRANK + DROPE)];
__device__ float g_cn  [T_SEQ * KVRANK];
__device__ float g_kv  [T_SEQ * NHEAD * (DNOPE + DV)];
__device__ float g_kf  [T_SEQ * NHEAD * DHEAD];
__device__ float g_vt  [NHEAD * DV * T_SEQ];
__device__ float g_sc  [(long long)NHEAD * T_SEQ * T_SEQ];
__device__ float g_ctx [T_SEQ * NHEAD * DV];
__device__ float g_hres[T_SEQ * DMODEL];
__device__ float g_x2  [T_SEQ * DMODEL];
__device__ float g_gu  [T_SEQ * 2 * IFF];
__device__ float g_y   [T_SEQ * IFF];
// tf32-rounded weight copies
__device__ float g_wqa [QRANK * DMODEL];
__device__ float g_wqb [(NHEAD * DHEAD) * QRANK];
__device__ float g_wkva[(KVRANK + DROPE) * DMODEL];
__device__ float g_wkvb[(NHEAD * (DNOPE + DV)) * KVRANK];
__device__ float g_wo  [DMODEL * DMODEL];
__device__ float g_wgu [(2 * IFF) * DMODEL];
__device__ float g_wdn [DMODEL * IFF];

// ---------------- helpers ----------------------------------------------------
__device__ __forceinline__ unsigned f2tf32(float f) {
    unsigned r;
    asm("cvt.rna.tf32.f32 %0, %1;" : "=r"(r) : "f"(f));
    return r;
}
__device__ __forceinline__ float rnd(float f) { return __uint_as_float(f2tf32(f)); }

__device__ __forceinline__ void mma8(float c[4], const unsigned a[4], const unsigned b[2]) {
    asm volatile(
        "mma.sync.aligned.m16n8k8.row.col.f32.tf32.tf32.f32 "
        "{%0,%1,%2,%3},{%4,%5,%6,%7},{%8,%9},{%0,%1,%2,%3};\n"
        : "+f"(c[0]), "+f"(c[1]), "+f"(c[2]), "+f"(c[3])
        : "r"(a[0]), "r"(a[1]), "r"(a[2]), "r"(a[3]),
          "r"(b[0]), "r"(b[1]));
}

__device__ __forceinline__ void cp16(unsigned dst, const void* src, bool pred) {
    asm volatile("cp.async.cg.shared.global [%0], [%1], 16, %2;\n"
                 :: "r"(dst), "l"(src), "r"(pred ? 16 : 0));
}
#define CP_COMMIT() asm volatile("cp.async.commit_group;\n" ::: "memory")
#define CP_WAIT1()  asm volatile("cp.async.wait_group 1;\n" ::: "memory")

// ---------------- tf32 tensor-core GEMM (TN): C[m,n] = sum_k A[m,k]*B[n,k] --
// R9 geometry: 128x128 tile, BK=32, 8 warps (2x4), warp 64x32 (4x4 m16n8k8).
// Inputs MUST be tf32-pre-rounded; shared holds bits, no in-loop cvt.
// grid = (ceil(N/128), M/128, batch). R: optional residual. roundC: rna-round C.
// causal: skip blocks fully above diagonal. kcap: clamp K to m0+128.
#define SST    36
#define STAGES 3
#define GSMEM_SZ (STAGES * 2 * 128 * SST * 4)

__global__ void __launch_bounds__(256, 2) gemm_tc(
    const float* __restrict__ A, int lda, long long sA,
    const float* __restrict__ B, int ldb, long long sB,
    float*       __restrict__ C, int ldc, long long sC,
    const float* __restrict__ R,
    int N, int K, int causal, int kcap, int roundC)
{
    extern __shared__ float sh[];
    float* Asm = sh;
    float* Bsm = sh + STAGES * 128 * SST;

    long long z = blockIdx.z;
    A += z * sA; B += z * sB; C += z * sC;
    int m0 = blockIdx.y * 128, n0 = blockIdx.x * 128;
    if (causal && n0 > m0 + 127) return;
    if (kcap) { int kl = m0 + 128; if (kl < K) K = kl; }

    int tid = threadIdx.x;
    int lr = tid >> 1, lcb = (tid & 1) << 4;
    int wid = tid >> 5, wm = wid & 1, wn = wid >> 1;
    int lane = tid & 31, g = lane >> 2, t = lane & 3;

    unsigned As_u = (unsigned)__cvta_generic_to_shared(Asm);
    unsigned Bs_u = (unsigned)__cvta_generic_to_shared(Bsm);

    const float* Ap = A + (long long)(m0 + lr) * lda + lcb;
    bool bok = (n0 + lr) < N;
    const float* Bp = B + (long long)(n0 + lr) * ldb + lcb;

    float acc[4][4][4];
#pragma unroll
    for (int i = 0; i < 4; i++)
#pragma unroll
        for (int j = 0; j < 4; j++)
#pragma unroll
            for (int e = 0; e < 4; e++) acc[i][j][e] = 0.f;

    int nk = K >> 5;

#define PREFETCH(K0, S) do {                                                  \
        unsigned abase = As_u + (((S) * 128 + lr) * SST + lcb) * 4;           \
        unsigned bbase = Bs_u + (((S) * 128 + lr) * SST + lcb) * 4;           \
        const float* ap = Ap + (K0);                                          \
        const float* bp = Bp + (K0);                                          \
        _Pragma("unroll")                                                     \
        for (int j = 0; j < 4; j++) {                                         \
            cp16(abase + j * 16, ap + j * 4, true);                           \
            cp16(bbase + j * 16, bp + j * 4, bok);                            \
        }                                                                     \
    } while (0)

    PREFETCH(0, 0);
    CP_COMMIT();
    if (nk > 1) PREFETCH(32, 1);
    CP_COMMIT();

    for (int it = 0; it < nk; it++) {
        CP_WAIT1();
        __syncthreads();
        if (it + 2 < nk) PREFETCH((it + 2) << 5, (it + 2) % STAGES);
        CP_COMMIT();

        const unsigned* Asu = (const unsigned*)(Asm + (it % STAGES) * 128 * SST);
        const unsigned* Bsu = (const unsigned*)(Bsm + (it % STAGES) * 128 * SST);
#pragma unroll
        for (int kk = 0; kk < 4; kk++) {
            unsigned a[4][4], b[4][2];
#pragma unroll
            for (int i = 0; i < 4; i++) {
                const unsigned* p = &Asu[(wm * 64 + i * 16 + g) * SST + kk * 8 + t];
                a[i][0] = p[0];
                a[i][1] = p[8 * SST];
                a[i][2] = p[4];
                a[i][3] = p[8 * SST + 4];
            }
#pragma unroll
            for (int j = 0; j < 4; j++) {
                const unsigned* p = &Bsu[(wn * 32 + j * 8 + g) * SST + kk * 8 + t];
                b[j][0] = p[0];
                b[j][1] = p[4];
            }
#pragma unroll
            for (int i = 0; i < 4; i++)
#pragma unroll
                for (int j = 0; j < 4; j++) mma8(acc[i][j], a[i], b[j]);
        }
        __syncthreads();
    }

#pragma unroll
    for (int i = 0; i < 4; i++) {
        int r0 = m0 + wm * 64 + i * 16 + g;
#pragma unroll
        for (int j = 0; j < 4; j++) {
            int c0 = n0 + wn * 32 + j * 8 + 2 * t;
            if (c0 < N) {
                float v0 = acc[i][j][0], v1 = acc[i][j][1];
                float v2 = acc[i][j][2], v3 = acc[i][j][3];
                if (R) {
                    v0 += R[(long long)r0 * ldc + c0];
                    v1 += R[(long long)r0 * ldc + c0 + 1];
                    v2 += R[(long long)(r0 + 8) * ldc + c0];
                    v3 += R[(long long)(r0 + 8) * ldc + c0 + 1];
                }
                if (roundC) { v0 = rnd(v0); v1 = rnd(v1); v2 = rnd(v2); v3 = rnd(v3); }
                *(float2*)&C[(long long)r0 * ldc + c0]       = make_float2(v0, v1);
                *(float2*)&C[(long long)(r0 + 8) * ldc + c0] = make_float2(v2, v3);
            }
        }
    }
}

// ---------------- weight rounding: out = tf32_rna(in) ------------------------
__global__ void __launch_bounds__(256) round_w(
    const float4* __restrict__ in, float4* __restrict__ out, int n4)
{
    for (int i = blockIdx.x * 256 + threadIdx.x; i < n4; i += gridDim.x * 256) {
        float4 v = in[i];
        v.x = rnd(v.x); v.y = rnd(v.y); v.z = rnd(v.z); v.w = rnd(v.w);
        out[i] = v;
    }
}

// ---------------- V transpose (kv already tf32-rounded) ----------------------
__global__ void __launch_bounds__(256) transpose_v(
    const float* __restrict__ kv, float* __restrict__ vt)
{
    __shared__ float tile[32][33];
    int hd0 = blockIdx.x * 32, t0 = blockIdx.y * 32;
    int x = threadIdx.x & 31, ybase = threadIdx.x >> 5;
    for (int y = ybase; y < 32; y += 8) {
        int hd = hd0 + x, tt = t0 + y;
        tile[y][x] = kv[(long long)tt * (NHEAD * 256) + (hd >> 7) * 256 + DNOPE + (hd & 127)];
    }
    __syncthreads();
    for (int y = ybase; y < 32; y += 8) {
        int hd = hd0 + y, tt = t0 + x;
        vt[(long long)hd * T_SEQ + tt] = tile[x][y];
    }
}

// ---------------- RMSNorm (tf32-rounded output) -------------------------------
__global__ void __launch_bounds__(256) rmsnorm_k(
    const float* __restrict__ in, int ldin,
    const float* __restrict__ w,
    float* __restrict__ out, int ldout, int cols)
{
    int r = blockIdx.x;
    const float* xr = in + (long long)r * ldin;
    float* orow = out + (long long)r * ldout;
    float s = 0.f;
    for (int i = threadIdx.x; i < cols; i += 256) { float a = xr[i]; s += a * a; }
#pragma unroll
    for (int o = 16; o; o >>= 1) s += __shfl_xor_sync(0xffffffffu, s, o);
    __shared__ float sred[8];
    __shared__ float srs;
    if ((threadIdx.x & 31) == 0) sred[threadIdx.x >> 5] = s;
    __syncthreads();
    if (threadIdx.x == 0) {
        float tot = 0.f;
#pragma unroll
        for (int i = 0; i < 8; i++) tot += sred[i];
        srs = rsqrtf(tot / (float)cols + EPSV);
    }
    __syncthreads();
    float rs = srs;
    for (int i = threadIdx.x; i < cols; i += 256)
        orow[i] = rnd(xr[i] * rs * w[i]);
}

// ---------------- RoPE on q_pe, in place (rounded) ----------------------------
__global__ void __launch_bounds__(256) rope_q(
    float* __restrict__ q, const float* __restrict__ cosb, const float* __restrict__ sinb)
{
    int t = blockIdx.x;
    int h = blockIdx.y * 8 + (threadIdx.x >> 5);
    int i = threadIdx.x & 31;
    float* p = q + ((long long)t * NHEAD + h) * DHEAD + DNOPE;
    float a = p[2 * i], b = p[2 * i + 1];
    float c = cosb[t * 32 + i], s = sinb[t * 32 + i];
    __syncwarp();
    p[i]      = rnd(a * c - b * s);
    p[i + 32] = rnd(a * s + b * c);
}

// ---------------- k_full: k_nope | broadcast(roped k_pe) ----------------------
__global__ void __launch_bounds__(256) build_kfull(
    const float* __restrict__ ckv, const float* __restrict__ kv,
    float* __restrict__ kf,
    const float* __restrict__ cosb, const float* __restrict__ sinb)
{
    int t = blockIdx.x;
    __shared__ float kpe[DROPE];
    if (threadIdx.x < 32) {
        int i = threadIdx.x;
        const float* kp = ckv + (long long)t * (KVRANK + DROPE) + KVRANK;
        float a = kp[2 * i], b = kp[2 * i + 1];
        float c = cosb[t * 32 + i], s = sinb[t * 32 + i];
        kpe[i]      = rnd(a * c - b * s);
        kpe[i + 32] = rnd(a * s + b * c);
    }
    __syncthreads();
    for (int idx = threadIdx.x; idx < NHEAD * DNOPE; idx += 256) {
        int h = idx >> 7, d = idx & 127;
        kf[((long long)t * NHEAD + h) * DHEAD + d] =
            kv[((long long)t * NHEAD + h) * (DNOPE + DV) + d];
    }
    for (int idx = threadIdx.x; idx < NHEAD * DROPE; idx += 256) {
        int h = idx >> 6, d = idx & 63;
        kf[((long long)t * NHEAD + h) * DHEAD + DNOPE + d] = kpe[d];
    }
}

// ---------------- causal softmax (scale fused, rounded), in place -------------
__global__ void __launch_bounds__(256) softmax_causal(float* __restrict__ S)
{
    int t = blockIdx.x;
    long long h = blockIdx.y;
    float* row = S + (h * T_SEQ + t) * (long long)T_SEQ;
    int n = t + 1;
    int tid = threadIdx.x;
    float v[4];
#pragma unroll
    for (int j = 0; j < 4; j++) {
        int i = tid + j * 256;
        v[j] = (i < n) ? row[i] * SCALEV : -3.0e38f;
    }
    float m = fmaxf(fmaxf(v[0], v[1]), fmaxf(v[2], v[3]));
#pragma unroll
    for (int o = 16; o; o >>= 1) m = fmaxf(m, __shfl_xor_sync(0xffffffffu, m, o));
    __shared__ float sred[8];
    __shared__ float sres;
    if ((tid & 31) == 0) sred[tid >> 5] = m;
    __syncthreads();
    if (tid == 0) {
        float x = sred[0];
#pragma unroll
        for (int i = 1; i < 8; i++) x = fmaxf(x, sred[i]);
        sres = x;
    }
    __syncthreads();
    m = sres;
    __syncthreads();
    float s = 0.f;
#pragma unroll
    for (int j = 0; j < 4; j++) { v[j] = __expf(v[j] - m); s += v[j]; }
#pragma unroll
    for (int o = 16; o; o >>= 1) s += __shfl_xor_sync(0xffffffffu, s, o);
    if ((tid & 31) == 0) sred[tid >> 5] = s;
    __syncthreads();
    if (tid == 0) {
        float x = 0.f;
#pragma unroll
        for (int i = 0; i < 8; i++) x += sred[i];
        sres = x;
    }
    __syncthreads();
    float inv = 1.f / sres;
#pragma unroll
    for (int j = 0; j < 4; j++) {
        int i = tid + j * 256;
        row[i] = rnd(v[j] * inv);
    }
}

// ---------------- silu(gate) * up (rounded) ----------------------------------
__global__ void __launch_bounds__(256) silu_mul(
    const float* __restrict__ gu, float* __restrict__ y)
{
    long long idx = (long long)blockIdx.x * 256 + threadIdx.x;
    int t = (int)(idx / IFF);
    int i = (int)(idx % IFF);
    float g = gu[(long long)t * (2 * IFF) + i];
    float u = gu[(long long)t * (2 * IFF) + IFF + i];
    y[idx] = rnd(g / (1.f + __expf(-g)) * u);
}

// ---------------- launch ----------------------------------------------------
extern "C" void kernel_launch(void* const* d_in, const int* in_sizes, int n_in,
                              void* d_out, int out_size)
{
    const float* hidden    = (const float*)d_in[0];
    const float* cosb      = (const float*)d_in[1];
    const float* sinb      = (const float*)d_in[2];
    const float* w_ln_in   = (const float*)d_in[3];
    const float* w_q_a     = (const float*)d_in[4];
    const float* w_q_ln    = (const float*)d_in[5];
    const float* w_q_b     = (const float*)d_in[6];
    const float* w_kv_a    = (const float*)d_in[7];
    const float* w_kv_ln   = (const float*)d_in[8];
    const float* w_kv_b    = (const float*)d_in[9];
    const float* w_o       = (const float*)d_in[10];
    const float* w_ln_post = (const float*)d_in[11];
    const float* w_gate_up = (const float*)d_in[12];
    const float* w_down    = (const float*)d_in[13];
    float* out = (float*)d_out;

    static int smem_set = 0;
    if (!smem_set) {
        cudaFuncSetAttribute(gemm_tc,
                             cudaFuncAttributeMaxDynamicSharedMemorySize, GSMEM_SZ);
        smem_set = 1;
    }

    float *x, *qa, *qan, *q, *ckv, *cn, *kv, *kf, *vt, *sc, *ctx, *hres, *x2, *gu, *y;
    float *wqa, *wqb, *wkva, *wkvb, *wo, *wgu, *wdn;
    cudaGetSymbolAddress((void**)&x,    g_x);
    cudaGetSymbolAddress((void**)&qa,   g_qa);
    cudaGetSymbolAddress((void**)&qan,  g_qan);
    cudaGetSymbolAddress((void**)&q,    g_q);
    cudaGetSymbolAddress((void**)&ckv,  g_ckv);
    cudaGetSymbolAddress((void**)&cn,   g_cn);
    cudaGetSymbolAddress((void**)&kv,   g_kv);
    cudaGetSymbolAddress((void**)&kf,   g_kf);
    cudaGetSymbolAddress((void**)&vt,   g_vt);
    cudaGetSymbolAddress((void**)&sc,   g_sc);
    cudaGetSymbolAddress((void**)&ctx,  g_ctx);
    cudaGetSymbolAddress((void**)&hres, g_hres);
    cudaGetSymbolAddress((void**)&x2,   g_x2);
    cudaGetSymbolAddress((void**)&gu,   g_gu);
    cudaGetSymbolAddress((void**)&y,    g_y);
    cudaGetSymbolAddress((void**)&wqa,  g_wqa);
    cudaGetSymbolAddress((void**)&wqb,  g_wqb);
    cudaGetSymbolAddress((void**)&wkva, g_wkva);
    cudaGetSymbolAddress((void**)&wkvb, g_wkvb);
    cudaGetSymbolAddress((void**)&wo,   g_wo);
    cudaGetSymbolAddress((void**)&wgu,  g_wgu);
    cudaGetSymbolAddress((void**)&wdn,  g_wdn);

    // 0. round all weights to tf32 (rna) once per call
    round_w<<<1184, 256>>>((const float4*)w_q_a,     (float4*)wqa,  QRANK * DMODEL / 4);
    round_w<<<1184, 256>>>((const float4*)w_q_b,     (float4*)wqb,  NHEAD * DHEAD * QRANK / 4);
    round_w<<<1184, 256>>>((const float4*)w_kv_a,    (float4*)wkva, (KVRANK + DROPE) * DMODEL / 4);
    round_w<<<1184, 256>>>((const float4*)w_kv_b,    (float4*)wkvb, NHEAD * 256 * KVRANK / 4);
    round_w<<<1184, 256>>>((const float4*)w_o,       (float4*)wo,   DMODEL * DMODEL / 4);
    round_w<<<1184, 256>>>((const float4*)w_gate_up, (float4*)wgu,  2 * IFF * DMODEL / 4);
    round_w<<<1184, 256>>>((const float4*)w_down,    (float4*)wdn,  DMODEL * IFF / 4);

    // 1. x = rmsnorm(hidden)  (tf32-rounded output)
    rmsnorm_k<<<T_SEQ, 256>>>(hidden, DMODEL, w_ln_in, x, DMODEL, DMODEL);
    // 2. q_a = x @ w_q_a^T
    gemm_tc<<<dim3(QRANK / 128, T_SEQ / 128, 1), 256, GSMEM_SZ>>>(
        x, DMODEL, 0, wqa, DMODEL, 0, qa, QRANK, 0, nullptr, QRANK, DMODEL, 0, 0, 0);
    // 3. q_a = rmsnorm(q_a)  (rounded)
    rmsnorm_k<<<T_SEQ, 256>>>(qa, QRANK, w_q_ln, qan, QRANK, QRANK);
    // 4. q = q_a @ w_q_b^T  (rounded: feeds QK)
    gemm_tc<<<dim3((NHEAD * DHEAD) / 128, T_SEQ / 128, 1), 256, GSMEM_SZ>>>(
        qan, QRANK, 0, wqb, QRANK, 0, q, NHEAD * DHEAD, 0, nullptr, NHEAD * DHEAD, QRANK, 0, 0, 1);
    // 5. ckv = x @ w_kv_a^T
    gemm_tc<<<dim3(5, T_SEQ / 128, 1), 256, GSMEM_SZ>>>(
        x, DMODEL, 0, wkva, DMODEL, 0, ckv, KVRANK + DROPE, 0, nullptr, KVRANK + DROPE, DMODEL, 0, 0, 0);
    // 6. c_n = rmsnorm(ckv[:, :512])  (rounded)
    rmsnorm_k<<<T_SEQ, 256>>>(ckv, KVRANK + DROPE, w_kv_ln, cn, KVRANK, KVRANK);
    // 7. kv = c_n @ w_kv_b^T  (rounded: feeds kf / vt)
    gemm_tc<<<dim3((NHEAD * 256) / 128, T_SEQ / 128, 1), 256, GSMEM_SZ>>>(
        cn, KVRANK, 0, wkvb, KVRANK, 0, kv, NHEAD * 256, 0, nullptr, NHEAD * 256, KVRANK, 0, 0, 1);
    // 8. rope q_pe in place (rounded)
    rope_q<<<dim3(T_SEQ, NHEAD / 8), 256>>>(q, cosb, sinb);
    // 9. k_full
    build_kfull<<<T_SEQ, 256>>>(ckv, kv, kf, cosb, sinb);
    // 9b. vt = V^T per head
    transpose_v<<<dim3((NHEAD * DV) / 32, T_SEQ / 32), 256>>>(kv, vt);
    // 10. scores = q @ kf^T  (batched; causal-skip)
    gemm_tc<<<dim3(T_SEQ / 128, T_SEQ / 128, NHEAD), 256, GSMEM_SZ>>>(
        q, NHEAD * DHEAD, (long long)DHEAD,
        kf, NHEAD * DHEAD, (long long)DHEAD,
        sc, T_SEQ, (long long)T_SEQ * T_SEQ,
        nullptr, T_SEQ, DHEAD, 1, 0, 0);
    // 11. causal softmax (rounded output)
    softmax_causal<<<dim3(T_SEQ, NHEAD), 256>>>(sc);
    // 12. ctx = probs @ vt^T  (K capped; rounded: feeds w_o GEMM)
    gemm_tc<<<dim3(1, T_SEQ / 128, NHEAD), 256, GSMEM_SZ>>>(
        sc, T_SEQ, (long long)T_SEQ * T_SEQ,
        vt, T_SEQ, (long long)DV * T_SEQ,
        ctx, NHEAD * DV, (long long)DV,
        nullptr, DV, T_SEQ, 0, 1, 1);
    // 13. h_res = ctx @ w_o^T + hidden  (NOT rounded: residual precision)
    gemm_tc<<<dim3(DMODEL / 128, T_SEQ / 128, 1), 256, GSMEM_SZ>>>(
        ctx, DMODEL, 0, wo, DMODEL, 0, hres, DMODEL, 0, hidden, DMODEL, DMODEL, 0, 0, 0);
    // 14. x2 = rmsnorm(h_res)  (rounded)
    rmsnorm_k<<<T_SEQ, 256>>>(hres, DMODEL, w_ln_post, x2, DMODEL, DMODEL);
    // 15. gu = x2 @ w_gate_up^T
    gemm_tc<<<dim3((2 * IFF) / 128, T_SEQ / 128, 1), 256, GSMEM_SZ>>>(
        x2, DMODEL, 0, wgu, DMODEL, 0, gu, 2 * IFF, 0, nullptr, 2 * IFF, DMODEL, 0, 0, 0);
    // 16. y = silu(gate) * up (rounded)
    silu_mul<<<(T_SEQ * IFF) / 256, 256>>>(gu, y);
    // 17. out = y @ w_down^T + h_res  (NOT rounded)
    gemm_tc<<<dim3(DMODEL / 128, T_SEQ / 128, 1), 256, GSMEM_SZ>>>(
        y, IFF, 0, wdn, IFF, 0, out, DMODEL, 0, hres, DMODEL, IFF, 0, 0, 0);
}

// round 15
// speedup vs baseline: 3.4559x; 2.0979x over previous
#include <cuda_runtime.h>
#include <cuda_fp16.h>
#include <math.h>

#define T_SEQ  1024
#define DMODEL 4096
#define NHEAD  32
#define DNOPE  128
#define DROPE  64
#define DHEAD  192
#define DV     128
#define QRANK  1536
#define KVRANK 512
#define IFF    11008
#define EPSV   1e-6f
#define SCALEV 0.07216878364870323f  // 192^-0.5
#define NQC    (QRANK + KVRANK + DROPE)   // 2112: merged q_a|kv_a output width

// ---------------- scratch ----------------------------------------------------
__device__ __half g_x   [T_SEQ * DMODEL];
__device__ float  g_qckv[T_SEQ * NQC];            // [qa | c | k_pe] fp32
__device__ __half g_qan [T_SEQ * QRANK];
__device__ __half g_cn  [T_SEQ * KVRANK];
__device__ __half g_q   [T_SEQ * NHEAD * DHEAD];
__device__ __half g_kv  [T_SEQ * NHEAD * (DNOPE + DV)];
__device__ __half g_kf  [T_SEQ * NHEAD * DHEAD];
__device__ __half g_vt  [NHEAD * DV * T_SEQ];
__device__ float  g_sc  [(long long)NHEAD * T_SEQ * T_SEQ];   // scores fp32
__device__ __half g_sch [(long long)NHEAD * T_SEQ * T_SEQ];   // probs half
__device__ __half g_ctx [T_SEQ * NHEAD * DV];
__device__ float  g_hres[T_SEQ * DMODEL];
__device__ __half g_x2  [T_SEQ * DMODEL];
__device__ float  g_gu  [T_SEQ * 2 * IFF];
__device__ __half g_y   [T_SEQ * IFF];
// fp16 weight copies
__device__ __half g_wqkva[NQC * DMODEL];
__device__ __half g_wqb  [(NHEAD * DHEAD) * QRANK];
__device__ __half g_wkvb [(NHEAD * (DNOPE + DV)) * KVRANK];
__device__ __half g_wo   [DMODEL * DMODEL];
__device__ __half g_wgu  [(2 * IFF) * DMODEL];
__device__ __half g_wdn  [DMODEL * IFF];

// ---------------- helpers ----------------------------------------------------
__device__ __forceinline__ void mma16(float c[4], const unsigned a[4], const unsigned b[2]) {
    asm volatile(
        "mma.sync.aligned.m16n8k16.row.col.f32.f16.f16.f32 "
        "{%0,%1,%2,%3},{%4,%5,%6,%7},{%8,%9},{%0,%1,%2,%3};\n"
        : "+f"(c[0]), "+f"(c[1]), "+f"(c[2]), "+f"(c[3])
        : "r"(a[0]), "r"(a[1]), "r"(a[2]), "r"(a[3]),
          "r"(b[0]), "r"(b[1]));
}

__device__ __forceinline__ void cp16(unsigned dst, const void* src, bool pred) {
    asm volatile("cp.async.cg.shared.global [%0], [%1], 16, %2;\n"
                 :: "r"(dst), "l"(src), "r"(pred ? 16 : 0));
}
#define CP_COMMIT() asm volatile("cp.async.commit_group;\n" ::: "memory")
#define CP_WAIT1()  asm volatile("cp.async.wait_group 1;\n" ::: "memory")

// ---------------- fp16 tensor-core GEMM (TN): C[m,n] = sum_k A[m,k]*B[n,k] --
// 128x128 CTA tile, BK=32, 8 warps (2x4), warp 64x32 via 4x4 m16n8k16.
// A,B fp16 in global; smem rows padded to 40 halves (80B) -> conflict-free LDS
// (bank = 20g + t, distinct for g=0..7,t=0..3). 3-stage cp.async pipeline.
// grid = (ceil(N/128), M/128, batch). C fp32 (optional fp32 residual R) or fp16.
// causal: skip blocks fully above diagonal. kcap: clamp K to m0+128.
#define SROW 40                    // halves per smem row
#define STGH (2 * 128 * SROW)      // halves per stage (A + B)
#define GSMEM_SZ (3 * STGH * 2)    // bytes

__global__ void __launch_bounds__(256, 2) gemm_h(
    const __half* __restrict__ A, int lda, long long sA,
    const __half* __restrict__ B, int ldb, long long sB,
    void*         __restrict__ C, int ldc, long long sC, int cHalf,
    const float*  __restrict__ R,
    int N, int K, int causal, int kcap)
{
    extern __shared__ __half sh[];
    long long z = blockIdx.z;
    A += z * sA; B += z * sB;
    int m0 = blockIdx.y * 128, n0 = blockIdx.x * 128;
    if (causal && n0 > m0 + 127) return;
    if (kcap) { int kl = m0 + 128; if (kl < K) K = kl; }

    int tid = threadIdx.x;
    int lr = tid >> 1, lc = (tid & 1) * 2;            // loader row, chunk base
    int wid = tid >> 5, wm = wid & 1, wn = wid >> 1;  // warps 2(M) x 4(N)
    int lane = tid & 31, g = lane >> 2, t = lane & 3;

    unsigned sh_u = (unsigned)__cvta_generic_to_shared(sh);
    const __half* Ap = A + (long long)(m0 + lr) * lda + lc * 8;
    bool bok = (n0 + lr) < N;
    const __half* Bp = B + (long long)(n0 + lr) * ldb + lc * 8;

    float acc[4][4][4];
#pragma unroll
    for (int i = 0; i < 4; i++)
#pragma unroll
        for (int j = 0; j < 4; j++)
#pragma unroll
            for (int e = 0; e < 4; e++) acc[i][j][e] = 0.f;

    int nk = K >> 5;

#define PREFETCH(K0, S) do {                                                   \
        unsigned ab = sh_u + ((S) * STGH + lr * SROW) * 2 + lc * 16;           \
        unsigned bb = ab + 128 * SROW * 2;                                     \
        const __half* ap = Ap + (K0);                                          \
        const __half* bp = Bp + (K0);                                          \
        cp16(ab,      ap,     true);                                           \
        cp16(ab + 16, ap + 8, true);                                           \
        cp16(bb,      bp,     bok);                                            \
        cp16(bb + 16, bp + 8, bok);                                            \
    } while (0)

    PREFETCH(0, 0);
    CP_COMMIT();
    if (nk > 1) PREFETCH(32, 1);
    CP_COMMIT();

    for (int it = 0; it < nk; it++) {
        CP_WAIT1();
        __syncthreads();
        if (it + 2 < nk) PREFETCH((it + 2) << 5, (it + 2) % 3);
        CP_COMMIT();

        const __half* As = sh + (it % 3) * STGH;
        const __half* Bs = As + 128 * SROW;
#pragma unroll
        for (int ks = 0; ks < 2; ks++) {
            unsigned a[4][4], b[4][2];
#pragma unroll
            for (int i = 0; i < 4; i++) {
                const __half* p = As + (wm * 64 + i * 16 + g) * SROW + ks * 16 + 2 * t;
                a[i][0] = *(const unsigned*)(p);
                a[i][1] = *(const unsigned*)(p + 8 * SROW);
                a[i][2] = *(const unsigned*)(p + 8);
                a[i][3] = *(const unsigned*)(p + 8 * SROW + 8);
            }
#pragma unroll
            for (int j = 0; j < 4; j++) {
                const __half* p = Bs + (wn * 32 + j * 8 + g) * SROW + ks * 16 + 2 * t;
                b[j][0] = *(const unsigned*)(p);
                b[j][1] = *(const unsigned*)(p + 8);
            }
#pragma unroll
            for (int i = 0; i < 4; i++)
#pragma unroll
                for (int j = 0; j < 4; j++) mma16(acc[i][j], a[i], b[j]);
        }
        __syncthreads();
    }

#pragma unroll
    for (int i = 0; i < 4; i++) {
        int r0 = m0 + wm * 64 + i * 16 + g;
#pragma unroll
        for (int j = 0; j < 4; j++) {
            int c0 = n0 + wn * 32 + j * 8 + 2 * t;
            if (c0 < N) {
                float v0 = acc[i][j][0], v1 = acc[i][j][1];
                float v2 = acc[i][j][2], v3 = acc[i][j][3];
                if (cHalf) {
                    __half* Ch = (__half*)C + z * sC;
                    __half2 h0 = __floats2half2_rn(v0, v1);
                    __half2 h1 = __floats2half2_rn(v2, v3);
                    *(unsigned*)&Ch[(long long)r0 * ldc + c0]       = *(unsigned*)&h0;
                    *(unsigned*)&Ch[(long long)(r0 + 8) * ldc + c0] = *(unsigned*)&h1;
                } else {
                    float* Cf = (float*)C + z * sC;
                    if (R) {
                        v0 += R[(long long)r0 * ldc + c0];
                        v1 += R[(long long)r0 * ldc + c0 + 1];
                        v2 += R[(long long)(r0 + 8) * ldc + c0];
                        v3 += R[(long long)(r0 + 8) * ldc + c0 + 1];
                    }
                    *(float2*)&Cf[(long long)r0 * ldc + c0]       = make_float2(v0, v1);
                    *(float2*)&Cf[(long long)(r0 + 8) * ldc + c0] = make_float2(v2, v3);
                }
            }
        }
    }
}

// ---------------- fp32 -> fp16 weight conversion ------------------------------
__global__ void __launch_bounds__(256) f2h(
    const float4* __restrict__ in, uint2* __restrict__ out, int n4)
{
    for (int i = blockIdx.x * 256 + threadIdx.x; i < n4; i += gridDim.x * 256) {
        float4 v = in[i];
        __half2 a = __floats2half2_rn(v.x, v.y);
        __half2 b = __floats2half2_rn(v.z, v.w);
        uint2 r;
        r.x = *(unsigned*)&a;
        r.y = *(unsigned*)&b;
        out[i] = r;
    }
}

// ---------------- V transpose: vt[h][d][t] = kv[t][h][128+d] (half) ----------
__global__ void __launch_bounds__(256) transpose_v(
    const __half* __restrict__ kv, __half* __restrict__ vt)
{
    __shared__ __half tile[32][33];
    int hd0 = blockIdx.x * 32, t0 = blockIdx.y * 32;
    int x = threadIdx.x & 31, ybase = threadIdx.x >> 5;
    for (int y = ybase; y < 32; y += 8) {
        int hd = hd0 + x, tt = t0 + y;
        tile[y][x] = kv[(long long)tt * (NHEAD * 256) + (hd >> 7) * 256 + DNOPE + (hd & 127)];
    }
    __syncthreads();
    for (int y = ybase; y < 32; y += 8) {
        int hd = hd0 + y, tt = t0 + x;
        vt[(long long)hd * T_SEQ + tt] = tile[x][y];
    }
}

// ---------------- RMSNorm: fp32 in, fp16 out ----------------------------------
__global__ void __launch_bounds__(256) rmsnorm_k(
    const float* __restrict__ in, int ldin,
    const float* __restrict__ w,
    __half* __restrict__ out, int ldout, int cols)
{
    int r = blockIdx.x;
    const float* xr = in + (long long)r * ldin;
    __half* orow = out + (long long)r * ldout;
    float s = 0.f;
    for (int i = threadIdx.x; i < cols; i += 256) { float a = xr[i]; s += a * a; }
#pragma unroll
    for (int o = 16; o; o >>= 1) s += __shfl_xor_sync(0xffffffffu, s, o);
    __shared__ float sred[8];
    __shared__ float srs;
    if ((threadIdx.x & 31) == 0) sred[threadIdx.x >> 5] = s;
    __syncthreads();
    if (threadIdx.x == 0) {
        float tot = 0.f;
#pragma unroll
        for (int i = 0; i < 8; i++) tot += sred[i];
        srs = rsqrtf(tot / (float)cols + EPSV);
    }
    __syncthreads();
    float rs = srs;
    for (int i = threadIdx.x; i < cols; i += 256)
        orow[i] = __float2half_rn(xr[i] * rs * w[i]);
}

// ---------------- RoPE on q_pe (half, in place) --------------------------------
__global__ void __launch_bounds__(256) rope_q(
    __half* __restrict__ q, const float* __restrict__ cosb, const float* __restrict__ sinb)
{
    int t = blockIdx.x;
    int h = blockIdx.y * 8 + (threadIdx.x >> 5);
    int i = threadIdx.x & 31;
    __half* p = q + ((long long)t * NHEAD + h) * DHEAD + DNOPE;
    __half2 v = ((const __half2*)p)[i];
    float a = __low2float(v), b = __high2float(v);
    float c = cosb[t * 32 + i], s = sinb[t * 32 + i];
    __syncwarp();
    p[i]      = __float2half_rn(a * c - b * s);
    p[i + 32] = __float2half_rn(a * s + b * c);
}

// ---------------- k_full: k_nope | broadcast(roped k_pe) -----------------------
__global__ void __launch_bounds__(256) build_kfull(
    const float* __restrict__ qckv, const __half* __restrict__ kv,
    __half* __restrict__ kf,
    const float* __restrict__ cosb, const float* __restrict__ sinb)
{
    int t = blockIdx.x;
    __shared__ __half kpe[DROPE];
    if (threadIdx.x < 32) {
        int i = threadIdx.x;
        const float* kp = qckv + (long long)t * NQC + (QRANK + KVRANK);
        float a = kp[2 * i], b = kp[2 * i + 1];
        float c = cosb[t * 32 + i], s = sinb[t * 32 + i];
        kpe[i]      = __float2half_rn(a * c - b * s);
        kpe[i + 32] = __float2half_rn(a * s + b * c);
    }
    __syncthreads();
    for (int idx = threadIdx.x; idx < NHEAD * DNOPE; idx += 256) {
        int h = idx >> 7, d = idx & 127;
        kf[((long long)t * NHEAD + h) * DHEAD + d] =
            kv[((long long)t * NHEAD + h) * (DNOPE + DV) + d];
    }
    for (int idx = threadIdx.x; idx < NHEAD * DROPE; idx += 256) {
        int h = idx >> 6, d = idx & 63;
        kf[((long long)t * NHEAD + h) * DHEAD + DNOPE + d] = kpe[d];
    }
}

// ---------------- causal softmax: fp32 scores -> fp16 probs --------------------
__global__ void __launch_bounds__(256) softmax_causal(
    const float* __restrict__ S, __half* __restrict__ P)
{
    int t = blockIdx.x;
    long long h = blockIdx.y;
    const float* row = S + (h * T_SEQ + t) * (long long)T_SEQ;
    __half* prow = P + (h * T_SEQ + t) * (long long)T_SEQ;
    int n = t + 1;
    int tid = threadIdx.x;
    float v[4];
#pragma unroll
    for (int j = 0; j < 4; j++) {
        int i = tid + j * 256;
        v[j] = (i < n) ? row[i] * SCALEV : -3.0e38f;
    }
    float m = fmaxf(fmaxf(v[0], v[1]), fmaxf(v[2], v[3]));
#pragma unroll
    for (int o = 16; o; o >>= 1) m = fmaxf(m, __shfl_xor_sync(0xffffffffu, m, o));
    __shared__ float sred[8];
    __shared__ float sres;
    if ((tid & 31) == 0) sred[tid >> 5] = m;
    __syncthreads();
    if (tid == 0) {
        float x = sred[0];
#pragma unroll
        for (int i = 1; i < 8; i++) x = fmaxf(x, sred[i]);
        sres = x;
    }
    __syncthreads();
    m = sres;
    __syncthreads();
    float s = 0.f;
#pragma unroll
    for (int j = 0; j < 4; j++) { v[j] = __expf(v[j] - m); s += v[j]; }
#pragma unroll
    for (int o = 16; o; o >>= 1) s += __shfl_xor_sync(0xffffffffu, s, o);
    if ((tid & 31) == 0) sred[tid >> 5] = s;
    __syncthreads();
    if (tid == 0) {
        float x = 0.f;
#pragma unroll
        for (int i = 0; i < 8; i++) x += sred[i];
        sres = x;
    }
    __syncthreads();
    float inv = 1.f / sres;
#pragma unroll
    for (int j = 0; j < 4; j++) {
        int i = tid + j * 256;
        prow[i] = __float2half_rn(v[j] * inv);
    }
}

// ---------------- silu(gate) * up: fp32 in, fp16 out ---------------------------
__global__ void __launch_bounds__(256) silu_mul(
    const float* __restrict__ gu, __half* __restrict__ y)
{
    long long idx = (long long)blockIdx.x * 256 + threadIdx.x;
    int t = (int)(idx / IFF);
    int i = (int)(idx % IFF);
    float g = gu[(long long)t * (2 * IFF) + i];
    float u = gu[(long long)t * (2 * IFF) + IFF + i];
    y[idx] = __float2half_rn(g / (1.f + __expf(-g)) * u);
}

// ---------------- launch ----------------------------------------------------
extern "C" void kernel_launch(void* const* d_in, const int* in_sizes, int n_in,
                              void* d_out, int out_size)
{
    const float* hidden    = (const float*)d_in[0];
    const float* cosb      = (const float*)d_in[1];
    const float* sinb      = (const float*)d_in[2];
    const float* w_ln_in   = (const float*)d_in[3];
    const float* w_q_a     = (const float*)d_in[4];
    const float* w_q_ln    = (const float*)d_in[5];
    const float* w_q_b     = (const float*)d_in[6];
    const float* w_kv_a    = (const float*)d_in[7];
    const float* w_kv_ln   = (const float*)d_in[8];
    const float* w_kv_b    = (const float*)d_in[9];
    const float* w_o       = (const float*)d_in[10];
    const float* w_ln_post = (const float*)d_in[11];
    const float* w_gate_up = (const float*)d_in[12];
    const float* w_down    = (const float*)d_in[13];
    float* out = (float*)d_out;

    static int smem_set = 0;
    if (!smem_set) {
        cudaFuncSetAttribute(gemm_h,
                             cudaFuncAttributeMaxDynamicSharedMemorySize, GSMEM_SZ);
        smem_set = 1;
    }

    __half *x, *qan, *cn, *q, *kv, *kf, *vt, *sch, *ctx, *x2, *y;
    __half *wqkva, *wqb, *wkvb, *wo, *wgu, *wdn;
    float *qckv, *sc, *hres, *gu;
    cudaGetSymbolAddress((void**)&x,     g_x);
    cudaGetSymbolAddress((void**)&qckv,  g_qckv);
    cudaGetSymbolAddress((void**)&qan,   g_qan);
    cudaGetSymbolAddress((void**)&cn,    g_cn);
    cudaGetSymbolAddress((void**)&q,     g_q);
    cudaGetSymbolAddress((void**)&kv,    g_kv);
    cudaGetSymbolAddress((void**)&kf,    g_kf);
    cudaGetSymbolAddress((void**)&vt,    g_vt);
    cudaGetSymbolAddress((void**)&sc,    g_sc);
    cudaGetSymbolAddress((void**)&sch,   g_sch);
    cudaGetSymbolAddress((void**)&ctx,   g_ctx);
    cudaGetSymbolAddress((void**)&hres,  g_hres);
    cudaGetSymbolAddress((void**)&x2,    g_x2);
    cudaGetSymbolAddress((void**)&gu,    g_gu);
    cudaGetSymbolAddress((void**)&y,     g_y);
    cudaGetSymbolAddress((void**)&wqkva, g_wqkva);
    cudaGetSymbolAddress((void**)&wqb,   g_wqb);
    cudaGetSymbolAddress((void**)&wkvb,  g_wkvb);
    cudaGetSymbolAddress((void**)&wo,    g_wo);
    cudaGetSymbolAddress((void**)&wgu,   g_wgu);
    cudaGetSymbolAddress((void**)&wdn,   g_wdn);

    // 0. convert all weights to fp16 once per call (q_a|kv_a merged buffer)
    f2h<<<1184, 256>>>((const float4*)w_q_a,     (uint2*)wqkva,
                       QRANK * DMODEL / 4);
    f2h<<<1184, 256>>>((const float4*)w_kv_a,    (uint2*)(wqkva + QRANK * DMODEL),
                       (KVRANK + DROPE) * DMODEL / 4);
    f2h<<<1184, 256>>>((const float4*)w_q_b,     (uint2*)wqb,  NHEAD * DHEAD * QRANK / 4);
    f2h<<<1184, 256>>>((const float4*)w_kv_b,    (uint2*)wkvb, NHEAD * 256 * KVRANK / 4);
    f2h<<<1184, 256>>>((const float4*)w_o,       (uint2*)wo,   DMODEL * DMODEL / 4);
    f2h<<<1184, 256>>>((const float4*)w_gate_up, (uint2*)wgu,  2 * IFF * DMODEL / 4);
    f2h<<<1184, 256>>>((const float4*)w_down,    (uint2*)wdn,  DMODEL * IFF / 4);

    // 1. x = rmsnorm(hidden)  (half)
    rmsnorm_k<<<T_SEQ, 256>>>(hidden, DMODEL, w_ln_in, x, DMODEL, DMODEL);
    // 2. qckv = x @ [w_q_a | w_kv_a]^T  (merged; fp32 out)
    gemm_h<<<dim3(17, 8, 1), 256, GSMEM_SZ>>>(
        x, DMODEL, 0, wqkva, DMODEL, 0, qckv, NQC, 0, 0, nullptr, NQC, DMODEL, 0, 0);
    // 3. q_a-norm and c-norm from slices  (half)
    rmsnorm_k<<<T_SEQ, 256>>>(qckv, NQC, w_q_ln, qan, QRANK, QRANK);
    rmsnorm_k<<<T_SEQ, 256>>>(qckv + QRANK, NQC, w_kv_ln, cn, KVRANK, KVRANK);
    // 4. q = qan @ w_q_b^T  (half out)
    gemm_h<<<dim3(48, 8, 1), 256, GSMEM_SZ>>>(
        qan, QRANK, 0, wqb, QRANK, 0, q, NHEAD * DHEAD, 0, 1, nullptr,
        NHEAD * DHEAD, QRANK, 0, 0);
    // 7. kv = cn @ w_kv_b^T  (half out)
    gemm_h<<<dim3(64, 8, 1), 256, GSMEM_SZ>>>(
        cn, KVRANK, 0, wkvb, KVRANK, 0, kv, NHEAD * 256, 0, 1, nullptr,
        NHEAD * 256, KVRANK, 0, 0);
    // 8. rope q_pe in place
    rope_q<<<dim3(T_SEQ, NHEAD / 8), 256>>>(q, cosb, sinb);
    // 9. k_full (half)
    build_kfull<<<T_SEQ, 256>>>(qckv, kv, kf, cosb, sinb);
    // 9b. vt = V^T per head (half)
    transpose_v<<<dim3((NHEAD * DV) / 32, T_SEQ / 32), 256>>>(kv, vt);
    // 10. scores = q @ kf^T  (fp32 out; batched over heads; causal-skip)
    gemm_h<<<dim3(8, 8, NHEAD), 256, GSMEM_SZ>>>(
        q, NHEAD * DHEAD, (long long)DHEAD,
        kf, NHEAD * DHEAD, (long long)DHEAD,
        sc, T_SEQ, (long long)T_SEQ * T_SEQ, 0,
        nullptr, T_SEQ, DHEAD, 1, 0);
    // 11. causal softmax: fp32 scores -> half probs
    softmax_causal<<<dim3(T_SEQ, NHEAD), 256>>>(sc, sch);
    // 12. ctx = probs @ vt^T  (half out; K capped at m0+128)
    gemm_h<<<dim3(1, 8, NHEAD), 256, GSMEM_SZ>>>(
        sch, T_SEQ, (long long)T_SEQ * T_SEQ,
        vt, T_SEQ, (long long)DV * T_SEQ,
        ctx, NHEAD * DV, (long long)DV, 1,
        nullptr, DV, T_SEQ, 0, 1);
    // 13. h_res = ctx @ w_o^T + hidden  (fp32)
    gemm_h<<<dim3(32, 8, 1), 256, GSMEM_SZ>>>(
        ctx, DMODEL, 0, wo, DMODEL, 0, hres, DMODEL, 0, 0, hidden, DMODEL, DMODEL, 0, 0);
    // 14. x2 = rmsnorm(h_res)  (half)
    rmsnorm_k<<<T_SEQ, 256>>>(hres, DMODEL, w_ln_post, x2, DMODEL, DMODEL);
    // 15. gu = x2 @ w_gate_up^T  (fp32 out)
    gemm_h<<<dim3(172, 8, 1), 256, GSMEM_SZ>>>(
        x2, DMODEL, 0, wgu, DMODEL, 0, gu, 2 * IFF, 0, 0, nullptr, 2 * IFF, DMODEL, 0, 0);
    // 16. y = silu(gate) * up  (half)
    silu_mul<<<(T_SEQ * IFF) / 256, 256>>>(gu, y);
    // 17. out = y @ w_down^T + h_res  (fp32)
    gemm_h<<<dim3(32, 8, 1), 256, GSMEM_SZ>>>(
        y, IFF, 0, wdn, IFF, 0, out, DMODEL, 0, 0, hres, DMODEL, IFF, 0, 0);
}